// round 2
// baseline (speedup 1.0000x reference)
#include <cuda_runtime.h>
#include <cuda_bf16.h>

// ---------------------------------------------------------------------------
// GNNConv: 4-layer GraphConv (PyG) + ReLU + LayerNorm (+residual), D=128.
//   layer l: y = agg @ W_rel[l] + b_rel[l] + x @ W_root[l]
//            agg[i] = sum_{e: dst[e]==i} x[src[e]]
//   l=0:       h = LN(relu(y))
//   l=1,2:     h = LN(relu(y + x))
//   l=3:       out = y
// ---------------------------------------------------------------------------

#define DIM   128
#define MAXN  100000
#define TILE_R 64
#define XSTRIDE 132   // padded row stride (floats) for x tiles in smem
#define GTHREADS 512

// scratch (static device globals: allocation-free per harness rules)
__device__ __align__(128) float g_agg [MAXN * DIM];
__device__ __align__(128) float g_bufA[MAXN * DIM];
__device__ __align__(128) float g_bufB[MAXN * DIM];

// ---------------------------------------------------------------------------
__global__ void zero_kernel(float4* __restrict__ p, int n4) {
    int i = blockIdx.x * blockDim.x + threadIdx.x;
    if (i < n4) p[i] = make_float4(0.f, 0.f, 0.f, 0.f);
}

// one warp per edge: 32 lanes x float4 = 128 floats
__global__ void scatter_kernel(const float* __restrict__ x,
                               const int* __restrict__ src,
                               const int* __restrict__ dst,
                               float* __restrict__ agg, int E) {
    int widx = (blockIdx.x * blockDim.x + threadIdx.x) >> 5;
    int lane = threadIdx.x & 31;
    if (widx >= E) return;
    int s = __ldg(src + widx);
    int d = __ldg(dst + widx);
    float4 v = __ldg(((const float4*)x) + s * (DIM / 4) + lane);
    float* p = agg + d * DIM + lane * 4;
    // vectorized fp32 reduction (sm_90+): 1 RED per 16B
    asm volatile("red.global.add.v4.f32 [%0], {%1, %2, %3, %4};"
                 :: "l"(p), "f"(v.x), "f"(v.y), "f"(v.z), "f"(v.w)
                 : "memory");
}

// ---------------------------------------------------------------------------
// Fused dual-GEMM + epilogue. Persistent blocks; weights cached in smem.
// Block: 512 threads = 32 row-groups (tr) x 16 col-groups (tc).
// Thread tile: 2 rows x 8 cols. Block tile: 64 rows x 128 cols.
// MODE 0: relu+LN   MODE 1: +residual, relu+LN   MODE 2: raw y
template <int MODE>
__global__ void __launch_bounds__(GTHREADS, 1)
fused_gemm_kernel(const float* __restrict__ agg,
                  const float* __restrict__ x,
                  const float* __restrict__ Wr,   // [DIM][DIM] (k-major)
                  const float* __restrict__ br,   // [DIM]
                  const float* __restrict__ Wt,   // [DIM][DIM]
                  const float* __restrict__ gamma,
                  const float* __restrict__ beta,
                  float* __restrict__ out, int nrows) {
    extern __shared__ float smem[];
    float* ws_r = smem;                          // DIM*DIM
    float* ws_t = ws_r + DIM * DIM;              // DIM*DIM
    float* xa   = ws_t + DIM * DIM;              // TILE_R * XSTRIDE
    float* xh   = xa + TILE_R * XSTRIDE;         // TILE_R * XSTRIDE

    const int tid = threadIdx.x;
    const int tc = tid & 15;
    const int tr = tid >> 4;       // 0..31
    const int c0 = tc * 8;
    const int r0 = tr * 2;

    // load both weight matrices into smem (float4)
    {
        const float4* wr4 = (const float4*)Wr;
        const float4* wt4 = (const float4*)Wt;
        float4* sr = (float4*)ws_r;
        float4* st = (float4*)ws_t;
        for (int i = tid; i < DIM * DIM / 4; i += GTHREADS) {
            sr[i] = __ldg(wr4 + i);
            st[i] = __ldg(wt4 + i);
        }
    }
    float bias[8], gam[8], bet[8];
#pragma unroll
    for (int j = 0; j < 8; j++) {
        bias[j] = __ldg(br + c0 + j);
        gam[j]  = __ldg(gamma + c0 + j);
        bet[j]  = __ldg(beta + c0 + j);
    }

    const float* xaR = xa + r0 * XSTRIDE;
    const float* xhR = xh + r0 * XSTRIDE;

    const int ntiles = (nrows + TILE_R - 1) / TILE_R;
    for (int tile = blockIdx.x; tile < ntiles; tile += gridDim.x) {
        const int row0 = tile * TILE_R;
        __syncthreads();  // previous tile fully consumed
        // stage x tiles (agg + h), zero-fill OOB rows
        for (int i = tid; i < TILE_R * (DIM / 4); i += GTHREADS) {
            int r = i >> 5, c4 = i & 31;
            int gr = row0 + r;
            float4 va, vh;
            if (gr < nrows) {
                va = __ldg(((const float4*)agg) + gr * (DIM / 4) + c4);
                vh = __ldg(((const float4*)x)   + gr * (DIM / 4) + c4);
            } else {
                va = make_float4(0.f, 0.f, 0.f, 0.f);
                vh = va;
            }
            ((float4*)(xa + r * XSTRIDE))[c4] = va;
            ((float4*)(xh + r * XSTRIDE))[c4] = vh;
        }
        __syncthreads();

        float acc[2][8];
#pragma unroll
        for (int i = 0; i < 2; i++)
#pragma unroll
            for (int j = 0; j < 8; j++) acc[i][j] = 0.f;

#pragma unroll 8
        for (int k = 0; k < DIM; k++) {
            float4 wr0 = *(const float4*)(ws_r + k * DIM + c0);
            float4 wr1 = *(const float4*)(ws_r + k * DIM + c0 + 4);
            float4 wt0 = *(const float4*)(ws_t + k * DIM + c0);
            float4 wt1 = *(const float4*)(ws_t + k * DIM + c0 + 4);
            float wr[8] = {wr0.x, wr0.y, wr0.z, wr0.w, wr1.x, wr1.y, wr1.z, wr1.w};
            float wt[8] = {wt0.x, wt0.y, wt0.z, wt0.w, wt1.x, wt1.y, wt1.z, wt1.w};
            float a[2], h[2];
#pragma unroll
            for (int i = 0; i < 2; i++) {
                a[i] = xaR[i * XSTRIDE + k];
                h[i] = xhR[i * XSTRIDE + k];
            }
#pragma unroll
            for (int i = 0; i < 2; i++)
#pragma unroll
                for (int j = 0; j < 8; j++)
                    acc[i][j] += a[i] * wr[j] + h[i] * wt[j];
        }

        // epilogue: bias (+residual) (+relu+LN), store
#pragma unroll
        for (int i = 0; i < 2; i++) {
            float v[8];
            float s = 0.f, s2 = 0.f;
#pragma unroll
            for (int j = 0; j < 8; j++) {
                float t = acc[i][j] + bias[j];
                if (MODE == 1) t += xhR[i * XSTRIDE + c0 + j];
                if (MODE != 2) t = fmaxf(t, 0.f);
                v[j] = t;
                if (MODE != 2) { s += t; s2 += t * t; }
            }
            if (MODE != 2) {
                // one row is covered by 16 consecutive lanes (tc=0..15),
                // 16-aligned within the warp; xor-reduce over those lanes
#pragma unroll
                for (int o = 8; o >= 1; o >>= 1) {
                    s  += __shfl_xor_sync(0xffffffffu, s,  o);
                    s2 += __shfl_xor_sync(0xffffffffu, s2, o);
                }
                float mean = s * (1.f / DIM);
                float var  = s2 * (1.f / DIM) - mean * mean;
                float rs   = rsqrtf(var + 1e-5f);
#pragma unroll
                for (int j = 0; j < 8; j++)
                    v[j] = (v[j] - mean) * rs * gam[j] + bet[j];
            }
            int gr = row0 + r0 + i;
            if (gr < nrows) {
                float4* o4 = (float4*)(out + gr * DIM + c0);
                o4[0] = make_float4(v[0], v[1], v[2], v[3]);
                o4[1] = make_float4(v[4], v[5], v[6], v[7]);
            }
        }
    }
}

// ---------------------------------------------------------------------------
static const int SMEM_BYTES =
    (2 * DIM * DIM + 2 * TILE_R * XSTRIDE) * (int)sizeof(float);  // 198656

extern "C" void kernel_launch(void* const* d_in, const int* in_sizes, int n_in,
                              void* d_out, int out_size) {
    const float* in_feat = (const float*)d_in[0];
    const int*   ei      = (const int*)d_in[1];
    const float* W_rel   = (const float*)d_in[2];
    const float* b_rel   = (const float*)d_in[3];
    const float* W_root  = (const float*)d_in[4];
    const float* gamma   = (const float*)d_in[5];
    const float* beta    = (const float*)d_in[6];
    float* out = (float*)d_out;

    const int N = in_sizes[0] / DIM;
    const int E = in_sizes[1] / 2;
    const int* src = ei;
    const int* dst = ei + E;

    float *agg, *bufA, *bufB;
    cudaGetSymbolAddress((void**)&agg,  g_agg);
    cudaGetSymbolAddress((void**)&bufA, g_bufA);
    cudaGetSymbolAddress((void**)&bufB, g_bufB);

    cudaFuncSetAttribute(fused_gemm_kernel<0>,
                         cudaFuncAttributeMaxDynamicSharedMemorySize, SMEM_BYTES);
    cudaFuncSetAttribute(fused_gemm_kernel<1>,
                         cudaFuncAttributeMaxDynamicSharedMemorySize, SMEM_BYTES);
    cudaFuncSetAttribute(fused_gemm_kernel<2>,
                         cudaFuncAttributeMaxDynamicSharedMemorySize, SMEM_BYTES);

    const int n4 = N * DIM / 4;
    const int zgrid = (n4 + 255) / 256;
    const int sgrid = (E + 7) / 8;     // 8 warps/block, 1 warp/edge
    const int ggrid = 148;             // persistent, 1 CTA/SM (smem-limited)

    auto run_layer = [&](const float* xin, float* xout, int l, int mode) {
        zero_kernel<<<zgrid, 256>>>((float4*)agg, n4);
        scatter_kernel<<<sgrid, 256>>>(xin, src, dst, agg, E);
        const float* Wr = W_rel  + (size_t)l * DIM * DIM;
        const float* Wt = W_root + (size_t)l * DIM * DIM;
        const float* bl = b_rel  + (size_t)l * DIM;
        if (mode == 0)
            fused_gemm_kernel<0><<<ggrid, GTHREADS, SMEM_BYTES>>>(
                agg, xin, Wr, bl, Wt, gamma, beta, xout, N);
        else if (mode == 1)
            fused_gemm_kernel<1><<<ggrid, GTHREADS, SMEM_BYTES>>>(
                agg, xin, Wr, bl, Wt, gamma, beta, xout, N);
        else
            fused_gemm_kernel<2><<<ggrid, GTHREADS, SMEM_BYTES>>>(
                agg, xin, Wr, bl, Wt, gamma, beta, xout, N);
    };

    run_layer(in_feat, bufA, 0, 0);
    run_layer(bufA,    bufB, 1, 1);
    run_layer(bufB,    bufA, 2, 1);
    run_layer(bufA,    out,  3, 2);
}

// round 4
// speedup vs baseline: 1.2480x; 1.2480x over previous
#include <cuda_runtime.h>
#include <cuda_bf16.h>

// ---------------------------------------------------------------------------
// GNNConv: 4-layer GraphConv (PyG) + ReLU + LayerNorm (+residual), D=128.
//   layer l: y = agg @ W_rel[l] + b_rel[l] + x @ W_root[l]
//            agg[i] = sum_{e: dst[e]==i} x[src[e]]
// Aggregation via per-launch CSR build (counting sort by dst) + warp-gather.
// ---------------------------------------------------------------------------

#define DIM   128
#define MAXN  100000
#define MAXE  1600000
#define TILE_R 64
#define XSTRIDE 132
#define GTHREADS 512
#define SCAN_B 1024

// scratch (static device globals: allocation-free per harness rules)
__device__ __align__(128) float g_agg [MAXN * DIM];
__device__ __align__(128) float g_bufA[MAXN * DIM];
__device__ __align__(128) float g_bufB[MAXN * DIM];
__device__ int g_cnt   [MAXN];
__device__ int g_rowptr[MAXN];
__device__ int g_cursor[MAXN];
__device__ int g_esrc  [MAXE];
__device__ int g_bsum  [1024];

// ---------------------------------------------------------------------------
// CSR build
__global__ void zero_cnt_kernel(int* __restrict__ cnt, int n) {
    int i = blockIdx.x * blockDim.x + threadIdx.x;
    if (i < n) cnt[i] = 0;
}

__global__ void hist_kernel(const int* __restrict__ dst,
                            int* __restrict__ cnt, int E) {
    int e = blockIdx.x * blockDim.x + threadIdx.x;
    if (e < E) atomicAdd(cnt + __ldg(dst + e), 1);
}

// block-level exclusive scan; writes per-block totals
__global__ void scan1_kernel(const int* __restrict__ cnt,
                             int* __restrict__ rowptr,
                             int* __restrict__ bsum, int n) {
    __shared__ int sh[SCAN_B];
    int t = threadIdx.x;
    int i = blockIdx.x * SCAN_B + t;
    int v = (i < n) ? cnt[i] : 0;
    sh[t] = v;
    __syncthreads();
#pragma unroll
    for (int off = 1; off < SCAN_B; off <<= 1) {
        int add = (t >= off) ? sh[t - off] : 0;
        __syncthreads();
        sh[t] += add;
        __syncthreads();
    }
    if (i < n) rowptr[i] = sh[t] - v;          // exclusive
    if (t == SCAN_B - 1) bsum[blockIdx.x] = sh[t];
}

__global__ void scan2_kernel(int* __restrict__ bsum, int nb) {
    if (threadIdx.x == 0 && blockIdx.x == 0) {
        int acc = 0;
        for (int i = 0; i < nb; i++) { int v = bsum[i]; bsum[i] = acc; acc += v; }
    }
}

__global__ void scan3_kernel(int* __restrict__ rowptr,
                             int* __restrict__ cursor,
                             const int* __restrict__ bsum, int n) {
    int i = blockIdx.x * blockDim.x + threadIdx.x;
    if (i < n) {
        int r = rowptr[i] + bsum[i / SCAN_B];
        rowptr[i] = r;
        cursor[i] = r;
    }
}

__global__ void fill_kernel(const int* __restrict__ src,
                            const int* __restrict__ dst,
                            int* __restrict__ cursor,
                            int* __restrict__ esrc, int E) {
    int e = blockIdx.x * blockDim.x + threadIdx.x;
    if (e < E) {
        int pos = atomicAdd(cursor + __ldg(dst + e), 1);
        esrc[pos] = __ldg(src + e);
    }
}

// ---------------------------------------------------------------------------
// one warp per dst node: registers hold the 128-float accumulator.
// 4-deep unroll: 4 outstanding row loads per warp to cover L2 latency.
__global__ void gather_kernel(const float* __restrict__ x,
                              const int* __restrict__ rowptr,
                              const int* __restrict__ cnt,
                              const int* __restrict__ esrc,
                              float* __restrict__ agg, int n) {
    int node = (blockIdx.x * blockDim.x + threadIdx.x) >> 5;
    int lane = threadIdx.x & 31;
    if (node >= n) return;
    int beg = __ldg(rowptr + node);
    int num = __ldg(cnt + node);
    const float4* x4 = (const float4*)x;
    float4 a0 = make_float4(0.f, 0.f, 0.f, 0.f);
    float4 a1 = a0, a2 = a0, a3 = a0;
    int i = 0;
    for (; i + 4 <= num; i += 4) {
        int s0 = __ldg(esrc + beg + i);
        int s1 = __ldg(esrc + beg + i + 1);
        int s2 = __ldg(esrc + beg + i + 2);
        int s3 = __ldg(esrc + beg + i + 3);
        float4 v0 = __ldg(x4 + s0 * (DIM / 4) + lane);
        float4 v1 = __ldg(x4 + s1 * (DIM / 4) + lane);
        float4 v2 = __ldg(x4 + s2 * (DIM / 4) + lane);
        float4 v3 = __ldg(x4 + s3 * (DIM / 4) + lane);
        a0.x += v0.x; a0.y += v0.y; a0.z += v0.z; a0.w += v0.w;
        a1.x += v1.x; a1.y += v1.y; a1.z += v1.z; a1.w += v1.w;
        a2.x += v2.x; a2.y += v2.y; a2.z += v2.z; a2.w += v2.w;
        a3.x += v3.x; a3.y += v3.y; a3.z += v3.z; a3.w += v3.w;
    }
    for (; i < num; i++) {
        int s0 = __ldg(esrc + beg + i);
        float4 v0 = __ldg(x4 + s0 * (DIM / 4) + lane);
        a0.x += v0.x; a0.y += v0.y; a0.z += v0.z; a0.w += v0.w;
    }
    a0.x += a1.x + a2.x + a3.x;
    a0.y += a1.y + a2.y + a3.y;
    a0.z += a1.z + a2.z + a3.z;
    a0.w += a1.w + a2.w + a3.w;
    ((float4*)agg)[node * (DIM / 4) + lane] = a0;
}

// ---------------------------------------------------------------------------
// Fused dual-GEMM + epilogue. Persistent blocks; weights cached in smem.
// Block: 512 threads = 32 row-groups (tr) x 16 col-groups (tc).
// Thread tile: 2 rows x 8 cols. Block tile: 64 rows x 128 cols.
// MODE 0: relu+LN   MODE 1: +residual, relu+LN   MODE 2: raw y
template <int MODE>
__global__ void __launch_bounds__(GTHREADS, 1)
fused_gemm_kernel(const float* __restrict__ agg,
                  const float* __restrict__ x,
                  const float* __restrict__ Wr,
                  const float* __restrict__ br,
                  const float* __restrict__ Wt,
                  const float* __restrict__ gamma,
                  const float* __restrict__ beta,
                  float* __restrict__ out, int nrows) {
    extern __shared__ float smem[];
    float* ws_r = smem;
    float* ws_t = ws_r + DIM * DIM;
    float* xa   = ws_t + DIM * DIM;
    float* xh   = xa + TILE_R * XSTRIDE;

    const int tid = threadIdx.x;
    const int tc = tid & 15;
    const int tr = tid >> 4;
    const int c0 = tc * 8;
    const int r0 = tr * 2;

    {
        const float4* wr4 = (const float4*)Wr;
        const float4* wt4 = (const float4*)Wt;
        float4* sr = (float4*)ws_r;
        float4* st = (float4*)ws_t;
        for (int i = tid; i < DIM * DIM / 4; i += GTHREADS) {
            sr[i] = __ldg(wr4 + i);
            st[i] = __ldg(wt4 + i);
        }
    }
    float bias[8], gam[8], bet[8];
#pragma unroll
    for (int j = 0; j < 8; j++) {
        bias[j] = __ldg(br + c0 + j);
        gam[j]  = __ldg(gamma + c0 + j);
        bet[j]  = __ldg(beta + c0 + j);
    }

    const float* xaR = xa + r0 * XSTRIDE;
    const float* xhR = xh + r0 * XSTRIDE;

    const int ntiles = (nrows + TILE_R - 1) / TILE_R;
    for (int tile = blockIdx.x; tile < ntiles; tile += gridDim.x) {
        const int row0 = tile * TILE_R;
        __syncthreads();
        for (int i = tid; i < TILE_R * (DIM / 4); i += GTHREADS) {
            int r = i >> 5, c4 = i & 31;
            int gr = row0 + r;
            float4 va, vh;
            if (gr < nrows) {
                va = __ldg(((const float4*)agg) + gr * (DIM / 4) + c4);
                vh = __ldg(((const float4*)x)   + gr * (DIM / 4) + c4);
            } else {
                va = make_float4(0.f, 0.f, 0.f, 0.f);
                vh = va;
            }
            ((float4*)(xa + r * XSTRIDE))[c4] = va;
            ((float4*)(xh + r * XSTRIDE))[c4] = vh;
        }
        __syncthreads();

        float acc[2][8];
#pragma unroll
        for (int i = 0; i < 2; i++)
#pragma unroll
            for (int j = 0; j < 8; j++) acc[i][j] = 0.f;

#pragma unroll 8
        for (int k = 0; k < DIM; k++) {
            float4 wr0 = *(const float4*)(ws_r + k * DIM + c0);
            float4 wr1 = *(const float4*)(ws_r + k * DIM + c0 + 4);
            float4 wt0 = *(const float4*)(ws_t + k * DIM + c0);
            float4 wt1 = *(const float4*)(ws_t + k * DIM + c0 + 4);
            float wr[8] = {wr0.x, wr0.y, wr0.z, wr0.w, wr1.x, wr1.y, wr1.z, wr1.w};
            float wt[8] = {wt0.x, wt0.y, wt0.z, wt0.w, wt1.x, wt1.y, wt1.z, wt1.w};
            float a[2], h[2];
#pragma unroll
            for (int i = 0; i < 2; i++) {
                a[i] = xaR[i * XSTRIDE + k];
                h[i] = xhR[i * XSTRIDE + k];
            }
#pragma unroll
            for (int i = 0; i < 2; i++)
#pragma unroll
                for (int j = 0; j < 8; j++)
                    acc[i][j] += a[i] * wr[j] + h[i] * wt[j];
        }

#pragma unroll
        for (int i = 0; i < 2; i++) {
            float v[8];
            float s = 0.f, s2 = 0.f;
#pragma unroll
            for (int j = 0; j < 8; j++) {
                float t = acc[i][j] + bias[j];
                if (MODE == 1) t += xhR[i * XSTRIDE + c0 + j];
                if (MODE != 2) t = fmaxf(t, 0.f);
                v[j] = t;
                if (MODE != 2) { s += t; s2 += t * t; }
            }
            if (MODE != 2) {
#pragma unroll
                for (int o = 8; o >= 1; o >>= 1) {
                    s  += __shfl_xor_sync(0xffffffffu, s,  o);
                    s2 += __shfl_xor_sync(0xffffffffu, s2, o);
                }
                float mean = s * (1.f / DIM);
                float var  = s2 * (1.f / DIM) - mean * mean;
                float rs   = rsqrtf(var + 1e-5f);
#pragma unroll
                for (int j = 0; j < 8; j++)
                    v[j] = (v[j] - mean) * rs * gam[j] + bet[j];
            }
            int gr = row0 + r0 + i;
            if (gr < nrows) {
                float4* o4 = (float4*)(out + gr * DIM + c0);
                o4[0] = make_float4(v[0], v[1], v[2], v[3]);
                o4[1] = make_float4(v[4], v[5], v[6], v[7]);
            }
        }
    }
}

// ---------------------------------------------------------------------------
static const int SMEM_BYTES =
    (2 * DIM * DIM + 2 * TILE_R * XSTRIDE) * (int)sizeof(float);  // 198656

extern "C" void kernel_launch(void* const* d_in, const int* in_sizes, int n_in,
                              void* d_out, int out_size) {
    const float* in_feat = (const float*)d_in[0];
    const int*   ei      = (const int*)d_in[1];
    const float* W_rel   = (const float*)d_in[2];
    const float* b_rel   = (const float*)d_in[3];
    const float* W_root  = (const float*)d_in[4];
    const float* gamma   = (const float*)d_in[5];
    const float* beta    = (const float*)d_in[6];
    float* out = (float*)d_out;

    const int N = in_sizes[0] / DIM;
    const int E = in_sizes[1] / 2;
    const int* src = ei;
    const int* dst = ei + E;

    float *agg, *bufA, *bufB;
    int *cnt, *rowptr, *cursor, *esrc, *bsum;
    cudaGetSymbolAddress((void**)&agg,    g_agg);
    cudaGetSymbolAddress((void**)&bufA,   g_bufA);
    cudaGetSymbolAddress((void**)&bufB,   g_bufB);
    cudaGetSymbolAddress((void**)&cnt,    g_cnt);
    cudaGetSymbolAddress((void**)&rowptr, g_rowptr);
    cudaGetSymbolAddress((void**)&cursor, g_cursor);
    cudaGetSymbolAddress((void**)&esrc,   g_esrc);
    cudaGetSymbolAddress((void**)&bsum,   g_bsum);

    cudaFuncSetAttribute(fused_gemm_kernel<0>,
                         cudaFuncAttributeMaxDynamicSharedMemorySize, SMEM_BYTES);
    cudaFuncSetAttribute(fused_gemm_kernel<1>,
                         cudaFuncAttributeMaxDynamicSharedMemorySize, SMEM_BYTES);
    cudaFuncSetAttribute(fused_gemm_kernel<2>,
                         cudaFuncAttributeMaxDynamicSharedMemorySize, SMEM_BYTES);

    // ---- CSR build (once per launch; structure shared across layers) ----
    const int nb = (N + SCAN_B - 1) / SCAN_B;
    zero_cnt_kernel<<<(N + 255) / 256, 256>>>(cnt, N);
    hist_kernel<<<(E + 255) / 256, 256>>>(dst, cnt, E);
    scan1_kernel<<<nb, SCAN_B>>>(cnt, rowptr, bsum, N);
    scan2_kernel<<<1, 32>>>(bsum, nb);
    scan3_kernel<<<(N + 255) / 256, 256>>>(rowptr, cursor, bsum, N);
    fill_kernel<<<(E + 255) / 256, 256>>>(src, dst, cursor, esrc, E);

    const int ggrid = 148;
    const int agrid = (N + 7) / 8;   // 8 warps/block, 1 warp/node

    auto run_layer = [&](const float* xin, float* xout, int l, int mode) {
        gather_kernel<<<agrid, 256>>>(xin, rowptr, cnt, esrc, agg, N);
        const float* Wr = W_rel  + (size_t)l * DIM * DIM;
        const float* Wt = W_root + (size_t)l * DIM * DIM;
        const float* bl = b_rel  + (size_t)l * DIM;
        if (mode == 0)
            fused_gemm_kernel<0><<<ggrid, GTHREADS, SMEM_BYTES>>>(
                agg, xin, Wr, bl, Wt, gamma, beta, xout, N);
        else if (mode == 1)
            fused_gemm_kernel<1><<<ggrid, GTHREADS, SMEM_BYTES>>>(
                agg, xin, Wr, bl, Wt, gamma, beta, xout, N);
        else
            fused_gemm_kernel<2><<<ggrid, GTHREADS, SMEM_BYTES>>>(
                agg, xin, Wr, bl, Wt, gamma, beta, xout, N);
    };

    run_layer(in_feat, bufA, 0, 0);
    run_layer(bufA,    bufB, 1, 1);
    run_layer(bufB,    bufA, 2, 1);
    run_layer(bufA,    out,  3, 2);
}

// round 5
// speedup vs baseline: 1.8266x; 1.4636x over previous
#include <cuda_runtime.h>
#include <cuda_bf16.h>

// ---------------------------------------------------------------------------
// GNNConv: 4-layer GraphConv (PyG) + ReLU + LayerNorm (+residual), D=128.
//   layer l: y = agg @ W_rel[l] + b_rel[l] + x @ W_root[l]
//            agg[i] = sum_{e: dst[e]==i} x[src[e]]
// CSR build (counting sort by dst) + warp-gather + fused dual-GEMM (f32x2).
// ---------------------------------------------------------------------------

#define DIM   128
#define MAXN  100000
#define MAXE  1600000
#define TILE_R 64
#define XSTRIDE 132
#define GTHREADS 512
#define SCAN_B 1024

__device__ __align__(128) float g_agg [MAXN * DIM];
__device__ __align__(128) float g_bufA[MAXN * DIM];
__device__ __align__(128) float g_bufB[MAXN * DIM];
__device__ int g_cnt   [MAXN];
__device__ int g_rowptr[MAXN];
__device__ int g_cursor[MAXN];
__device__ int g_esrc  [MAXE];
__device__ int g_bsum  [1024];

// ---------------------------------------------------------------------------
// f32x2 helpers (Blackwell packed fp32 pipe; bit-identical to scalar FFMA)
typedef unsigned long long u64;
__device__ __forceinline__ void f2fma(u64& d, u64 a, u64 b) {
    asm("fma.rn.f32x2 %0, %1, %2, %0;" : "+l"(d) : "l"(a), "l"(b));
}
__device__ __forceinline__ float2 unpk(u64 v) {
    float2 r;
    asm("mov.b64 {%0, %1}, %2;" : "=f"(r.x), "=f"(r.y) : "l"(v));
    return r;
}

// ---------------------------------------------------------------------------
// CSR build
__global__ void hist_kernel(const int* __restrict__ dst,
                            int* __restrict__ cnt, int E) {
    int e = blockIdx.x * blockDim.x + threadIdx.x;
    if (e < E) atomicAdd(cnt + __ldg(dst + e), 1);
}

__global__ void scan1_kernel(const int* __restrict__ cnt,
                             int* __restrict__ rowptr,
                             int* __restrict__ bsum, int n) {
    __shared__ int sh[SCAN_B];
    int t = threadIdx.x;
    int i = blockIdx.x * SCAN_B + t;
    int v = (i < n) ? cnt[i] : 0;
    sh[t] = v;
    __syncthreads();
#pragma unroll
    for (int off = 1; off < SCAN_B; off <<= 1) {
        int add = (t >= off) ? sh[t - off] : 0;
        __syncthreads();
        sh[t] += add;
        __syncthreads();
    }
    if (i < n) rowptr[i] = sh[t] - v;          // exclusive
    if (t == SCAN_B - 1) bsum[blockIdx.x] = sh[t];
}

// adds prefix of bsum (warp-parallel, nb<=98) and seeds cursor
__global__ void scan3_kernel(int* __restrict__ rowptr,
                             int* __restrict__ cursor,
                             const int* __restrict__ bsum, int n) {
    __shared__ int sbase;
    int sb = (blockIdx.x * 256) / SCAN_B;      // owning scan1 block (256|1024)
    if (threadIdx.x < 32) {
        int p = 0;
        for (int j = threadIdx.x; j < sb; j += 32) p += __ldg(bsum + j);
#pragma unroll
        for (int o = 16; o >= 1; o >>= 1) p += __shfl_xor_sync(0xffffffffu, p, o);
        if (threadIdx.x == 0) sbase = p;
    }
    __syncthreads();
    int i = blockIdx.x * 256 + threadIdx.x;
    if (i < n) {
        int r = rowptr[i] + sbase;
        rowptr[i] = r;
        cursor[i] = r;
    }
}

__global__ void fill_kernel(const int* __restrict__ src,
                            const int* __restrict__ dst,
                            int* __restrict__ cursor,
                            int* __restrict__ esrc, int E) {
    int e = blockIdx.x * blockDim.x + threadIdx.x;
    if (e < E) {
        int pos = atomicAdd(cursor + __ldg(dst + e), 1);
        esrc[pos] = __ldg(src + e);
    }
}

// ---------------------------------------------------------------------------
// one warp per dst node; 8 outstanding row loads to cover L2 latency
__global__ void gather_kernel(const float* __restrict__ x,
                              const int* __restrict__ rowptr,
                              const int* __restrict__ cnt,
                              const int* __restrict__ esrc,
                              float* __restrict__ agg, int n) {
    int node = (blockIdx.x * blockDim.x + threadIdx.x) >> 5;
    int lane = threadIdx.x & 31;
    if (node >= n) return;
    int beg = __ldg(rowptr + node);
    int num = __ldg(cnt + node);
    const float4* x4 = (const float4*)x;
    float4 acc[8];
#pragma unroll
    for (int j = 0; j < 8; j++) acc[j] = make_float4(0.f, 0.f, 0.f, 0.f);
    int i = 0;
    for (; i + 8 <= num; i += 8) {
        int s[8];
#pragma unroll
        for (int j = 0; j < 8; j++) s[j] = __ldg(esrc + beg + i + j);
        float4 v[8];
#pragma unroll
        for (int j = 0; j < 8; j++) v[j] = __ldg(x4 + s[j] * (DIM / 4) + lane);
#pragma unroll
        for (int j = 0; j < 8; j++) {
            acc[j].x += v[j].x; acc[j].y += v[j].y;
            acc[j].z += v[j].z; acc[j].w += v[j].w;
        }
    }
    for (; i < num; i++) {
        int s0 = __ldg(esrc + beg + i);
        float4 v0 = __ldg(x4 + s0 * (DIM / 4) + lane);
        acc[0].x += v0.x; acc[0].y += v0.y; acc[0].z += v0.z; acc[0].w += v0.w;
    }
#pragma unroll
    for (int j = 1; j < 8; j++) {
        acc[0].x += acc[j].x; acc[0].y += acc[j].y;
        acc[0].z += acc[j].z; acc[0].w += acc[j].w;
    }
    ((float4*)agg)[node * (DIM / 4) + lane] = acc[0];
}

// ---------------------------------------------------------------------------
// Fused dual-GEMM + epilogue, f32x2 mainloop.
// 512 threads: tc = tid&15 (16 col groups), tr = tid>>4 (32 row groups).
// Thread tile: 2 rows x 8 cols, cols c_j = tc + 16*j (128B-contiguous weight
// reads). Accumulators pair even/odd k in one f32x2 lane pair.
// Weights in smem k-interleaved: wp[k>>2][c][k&3]  (float4 granules per col).
// MODE 0: relu+LN   MODE 1: +residual, relu+LN   MODE 2: raw y
template <int MODE>
__global__ void __launch_bounds__(GTHREADS, 1)
fused_gemm_kernel(const float* __restrict__ agg,
                  const float* __restrict__ x,
                  const float* __restrict__ Wr,
                  const float* __restrict__ br,
                  const float* __restrict__ Wt,
                  const float* __restrict__ gamma,
                  const float* __restrict__ beta,
                  float* __restrict__ out, int nrows) {
    extern __shared__ float smem[];
    float* wpR = smem;                       // DIM*DIM (k-interleaved)
    float* wpT = wpR + DIM * DIM;            // DIM*DIM
    float* xa  = wpT + DIM * DIM;            // TILE_R * XSTRIDE
    float* xh  = xa + TILE_R * XSTRIDE;      // TILE_R * XSTRIDE
    float* sbias = xh + TILE_R * XSTRIDE;    // DIM
    float* sgam  = sbias + DIM;              // DIM
    float* sbet  = sgam + DIM;               // DIM

    const int tid = threadIdx.x;
    const int tc = tid & 15;
    const int tr = tid >> 4;
    const int r0 = tr * 2;

    // stage weights (k-interleaved transpose) + epilogue params
    for (int idx = tid; idx < DIM * DIM; idx += GTHREADS) {
        int k = idx >> 7, c = idx & 127;
        int doff = ((k >> 2) * DIM + c) * 4 + (k & 3);
        wpR[doff] = __ldg(Wr + idx);
        wpT[doff] = __ldg(Wt + idx);
    }
    if (tid < DIM) {
        sbias[tid] = __ldg(br + tid);
        sgam[tid]  = __ldg(gamma + tid);
        sbet[tid]  = __ldg(beta + tid);
    }

    const float* xaR = xa + r0 * XSTRIDE;
    const float* xhR = xh + r0 * XSTRIDE;

    const int ntiles = (nrows + TILE_R - 1) / TILE_R;
    for (int tile = blockIdx.x; tile < ntiles; tile += gridDim.x) {
        const int row0 = tile * TILE_R;
        __syncthreads();  // previous tile consumed / weights staged
        for (int i = tid; i < TILE_R * (DIM / 4); i += GTHREADS) {
            int r = i >> 5, c4 = i & 31;
            int gr = row0 + r;
            float4 va, vh;
            if (gr < nrows) {
                va = __ldg(((const float4*)agg) + gr * (DIM / 4) + c4);
                vh = __ldg(((const float4*)x)   + gr * (DIM / 4) + c4);
            } else {
                va = make_float4(0.f, 0.f, 0.f, 0.f);
                vh = va;
            }
            ((float4*)(xa + r * XSTRIDE))[c4] = va;
            ((float4*)(xh + r * XSTRIDE))[c4] = vh;
        }
        __syncthreads();

        u64 acc[2][8];
#pragma unroll
        for (int i = 0; i < 2; i++)
#pragma unroll
            for (int j = 0; j < 8; j++) acc[i][j] = 0ull;

#pragma unroll 4
        for (int kq = 0; kq < DIM / 4; kq++) {
            const int k = kq * 4;
            // a/h: two f32x2 per row (k..k+1, k+2..k+3); lanes share tr -> broadcast
            u64 aL[2], aH[2], hL[2], hH[2];
#pragma unroll
            for (int i = 0; i < 2; i++) {
                aL[i] = *(const u64*)(xaR + i * XSTRIDE + k);
                aH[i] = *(const u64*)(xaR + i * XSTRIDE + k + 2);
                hL[i] = *(const u64*)(xhR + i * XSTRIDE + k);
                hH[i] = *(const u64*)(xhR + i * XSTRIDE + k + 2);
            }
            const float* wr_base = wpR + kq * DIM * 4;
            const float* wt_base = wpT + kq * DIM * 4;
#pragma unroll
            for (int j = 0; j < 8; j++) {
                const int c = tc + 16 * j;
                u64 wrL = *(const u64*)(wr_base + c * 4);
                u64 wrH = *(const u64*)(wr_base + c * 4 + 2);
                u64 wtL = *(const u64*)(wt_base + c * 4);
                u64 wtH = *(const u64*)(wt_base + c * 4 + 2);
#pragma unroll
                for (int i = 0; i < 2; i++) {
                    f2fma(acc[i][j], aL[i], wrL);
                    f2fma(acc[i][j], hL[i], wtL);
                    f2fma(acc[i][j], aH[i], wrH);
                    f2fma(acc[i][j], hH[i], wtH);
                }
            }
        }

        // epilogue
#pragma unroll
        for (int i = 0; i < 2; i++) {
            float v[8];
            float s = 0.f, s2 = 0.f;
#pragma unroll
            for (int j = 0; j < 8; j++) {
                const int c = tc + 16 * j;
                float2 p = unpk(acc[i][j]);
                float t = p.x + p.y + sbias[c];
                if (MODE == 1) t += xhR[i * XSTRIDE + c];
                if (MODE != 2) t = fmaxf(t, 0.f);
                v[j] = t;
                if (MODE != 2) { s += t; s2 += t * t; }
            }
            if (MODE != 2) {
                // full row lives in a 16-lane, 16-aligned group
#pragma unroll
                for (int o = 8; o >= 1; o >>= 1) {
                    s  += __shfl_xor_sync(0xffffffffu, s,  o);
                    s2 += __shfl_xor_sync(0xffffffffu, s2, o);
                }
                float mean = s * (1.f / DIM);
                float var  = s2 * (1.f / DIM) - mean * mean;
                float rs   = rsqrtf(var + 1e-5f);
#pragma unroll
                for (int j = 0; j < 8; j++) {
                    const int c = tc + 16 * j;
                    v[j] = (v[j] - mean) * rs * sgam[c] + sbet[c];
                }
            }
            int gr = row0 + r0 + i;
            if (gr < nrows) {
                float* orow = out + (size_t)gr * DIM;
#pragma unroll
                for (int j = 0; j < 8; j++) orow[tc + 16 * j] = v[j];
            }
        }
    }
}

// ---------------------------------------------------------------------------
static const int SMEM_BYTES =
    (2 * DIM * DIM + 2 * TILE_R * XSTRIDE + 3 * DIM) * (int)sizeof(float);

extern "C" void kernel_launch(void* const* d_in, const int* in_sizes, int n_in,
                              void* d_out, int out_size) {
    const float* in_feat = (const float*)d_in[0];
    const int*   ei      = (const int*)d_in[1];
    const float* W_rel   = (const float*)d_in[2];
    const float* b_rel   = (const float*)d_in[3];
    const float* W_root  = (const float*)d_in[4];
    const float* gamma   = (const float*)d_in[5];
    const float* beta    = (const float*)d_in[6];
    float* out = (float*)d_out;

    const int N = in_sizes[0] / DIM;
    const int E = in_sizes[1] / 2;
    const int* src = ei;
    const int* dst = ei + E;

    float *agg, *bufA, *bufB;
    int *cnt, *rowptr, *cursor, *esrc, *bsum;
    cudaGetSymbolAddress((void**)&agg,    g_agg);
    cudaGetSymbolAddress((void**)&bufA,   g_bufA);
    cudaGetSymbolAddress((void**)&bufB,   g_bufB);
    cudaGetSymbolAddress((void**)&cnt,    g_cnt);
    cudaGetSymbolAddress((void**)&rowptr, g_rowptr);
    cudaGetSymbolAddress((void**)&cursor, g_cursor);
    cudaGetSymbolAddress((void**)&esrc,   g_esrc);
    cudaGetSymbolAddress((void**)&bsum,   g_bsum);

    cudaFuncSetAttribute(fused_gemm_kernel<0>,
                         cudaFuncAttributeMaxDynamicSharedMemorySize, SMEM_BYTES);
    cudaFuncSetAttribute(fused_gemm_kernel<1>,
                         cudaFuncAttributeMaxDynamicSharedMemorySize, SMEM_BYTES);
    cudaFuncSetAttribute(fused_gemm_kernel<2>,
                         cudaFuncAttributeMaxDynamicSharedMemorySize, SMEM_BYTES);

    // ---- CSR build (once per launch; structure shared across layers) ----
    const int nb = (N + SCAN_B - 1) / SCAN_B;
    cudaMemsetAsync(cnt, 0, (size_t)N * sizeof(int));         // not a kernel
    hist_kernel<<<(E + 255) / 256, 256>>>(dst, cnt, E);       // launch 1
    scan1_kernel<<<nb, SCAN_B>>>(cnt, rowptr, bsum, N);       // launch 2
    scan3_kernel<<<(N + 255) / 256, 256>>>(rowptr, cursor, bsum, N); // 3
    fill_kernel<<<(E + 255) / 256, 256>>>(src, dst, cursor, esrc, E); // 4

    const int ggrid = 148;
    const int agrid = (N + 7) / 8;   // 8 warps/block, 1 warp/node

    auto run_layer = [&](const float* xin, float* xout, int l, int mode) {
        gather_kernel<<<agrid, 256>>>(xin, rowptr, cnt, esrc, agg, N);
        const float* Wr = W_rel  + (size_t)l * DIM * DIM;
        const float* Wt = W_root + (size_t)l * DIM * DIM;
        const float* bl = b_rel  + (size_t)l * DIM;
        if (mode == 0)
            fused_gemm_kernel<0><<<ggrid, GTHREADS, SMEM_BYTES>>>(
                agg, xin, Wr, bl, Wt, gamma, beta, xout, N);
        else if (mode == 1)
            fused_gemm_kernel<1><<<ggrid, GTHREADS, SMEM_BYTES>>>(
                agg, xin, Wr, bl, Wt, gamma, beta, xout, N);
        else
            fused_gemm_kernel<2><<<ggrid, GTHREADS, SMEM_BYTES>>>(
                agg, xin, Wr, bl, Wt, gamma, beta, xout, N);
    };

    run_layer(in_feat, bufA, 0, 0);   // launches 5,6  (ncu -s 5 captures #6 = gemm)
    run_layer(bufA,    bufB, 1, 1);
    run_layer(bufB,    bufA, 2, 1);
    run_layer(bufA,    out,  3, 2);
}